// round 12
// baseline (speedup 1.0000x reference)
#include <cuda_runtime.h>
#include <math.h>

#define NNODES 32768
#define BINCAP 128

__device__ float  g_Wc[3 * 16 * 32];              // combined W_pre@W_post for l=1..3, scaled
__device__ int    g_count[NNODES];
__device__ int    g_bin[(size_t)NNODES * BINCAP]; // sender ids grouped by receiver
__device__ float4 g_pos4[NNODES];                 // padded positions

// ---------- zero counts ----------
__global__ void zero_count_kernel() {
    int i = blockIdx.x * blockDim.x + threadIdx.x;
    if (i < NNODES) g_count[i] = 0;
}

// ---------- padded pos ----------
__global__ void pos4_kernel(const float* __restrict__ pos) {
    int i = blockIdx.x * blockDim.x + threadIdx.x;
    if (i < NNODES)
        g_pos4[i] = make_float4(pos[i * 3 + 0], pos[i * 3 + 1], pos[i * 3 + 2], 0.f);
}

// ---------- single-pass binning ----------
__global__ void scatter_bin_kernel(const int* __restrict__ senders,
                                   const int* __restrict__ receivers, int E) {
    int e = blockIdx.x * blockDim.x + threadIdx.x;
    if (e < E) {
        int r = receivers[e];
        int p = atomicAdd(&g_count[r], 1);
        if (p < BINCAP) g_bin[(size_t)r * BINCAP + p] = senders[e];
    }
}

// ---------- combined weights ----------
__global__ void wc_kernel(const float* __restrict__ W_pre, const float* __restrict__ W_post) {
    int t = blockIdx.x * blockDim.x + threadIdx.x;
    if (t >= 1536) return;
    int lm  = t >> 9;
    int rem = t & 511;
    int u = rem >> 5, w = rem & 31;
    const float* wp = W_pre  + (lm + 1) * 512  + u * 32;
    const float* wq = W_post + (lm + 1) * 1024 + w;
    float s = 0.f;
    #pragma unroll
    for (int v = 0; v < 32; v++) s += wp[v] * wq[v * 32];
    g_Wc[t] = s * (1.0f / 32.0f) * 0.25f * 0.17677669529663688f;
}

// Per-warp scratch: 1280 floats (5120 B).
// Lifetime 1 (edge loop):  Y[32][20] at [0..640), Xv[32][20] at [640..1280)
// Lifetime 2 (node phase): A[256] at [0..256), Xrow[16] at [256..272), Out[512] at [272..784)
#define WSCR 1280

#define FMA2(d, a, b, c) \
    asm("fma.rn.f32x2 %0, %1, %2, %3;" : "=l"(d) : "l"(a), "l"(b), "l"(c))

// ---------- fused gather + node update: 1 warp per node, 8 nodes/block ----------
__global__ void __launch_bounds__(256, 4) fused_kernel(
        const float* __restrict__ x,
        const float* __restrict__ W_pre,
        const float* __restrict__ W_post,
        const float* __restrict__ W_sc,
        float* __restrict__ out) {
    __shared__ float sWpre0[512];
    __shared__ float sWpost0[1024];
    __shared__ float sWsc[512];
    __shared__ float sWc[1536];
    __shared__ float sScr[8 * WSCR];

    int tid = threadIdx.x;
    const float invin = 0.25f, invmid = 0.17677669529663688f;
    for (int i = tid; i < 512;  i += 256) sWpre0[i]  = W_pre[i]  * (invin / 32.f);
    for (int i = tid; i < 1024; i += 256) sWpost0[i] = W_post[i] * invmid;
    for (int i = tid; i < 512;  i += 256) sWsc[i]    = W_sc[i]   * invin;
    for (int i = tid; i < 1536; i += 256) sWc[i]     = g_Wc[i];
    __syncthreads();

    int lane = tid & 31;
    int wp   = tid >> 5;
    int u    = lane & 15;             // phase-B mul channel
    int h    = lane >> 4;             // phase-B i-half
    int n    = blockIdx.x * 8 + wp;

    float* scr = sScr + wp * WSCR;
    float* sY  = scr;                 // [32][20]
    float* sXv = scr + 640;           // [32][20]

    float4 rp = g_pos4[n];
    float rx = rp.x, ry = rp.y, rz = rp.z;

    int deg = g_count[n];
    if (deg > BINCAP) deg = BINCAP;

    // packed accumulator pairs: (i0,i1)(i2,i3)(i4,i5)(i6,i7) for this lane's half
    unsigned long long acc01 = 0ull, acc23 = 0ull, acc45 = 0ull, acc67 = 0ull;

    const float s3 = 1.7320508075688772f, s5 = 2.2360679774997896f,
                s15 = 3.872983346207417f, s7 = 2.6457513110645907f,
                s105 = 10.246950765959598f, s35_8 = 2.091650066335189f,
                s21_8 = 1.6201851746019651f;

    const int* binrow = g_bin + (size_t)n * BINCAP;
    const float4* x4  = reinterpret_cast<const float4*>(x);

    int chunk = lane & 3;             // cooperative x staging: 16B chunk
    int egrp  = lane >> 2;            // edge within group of 8

    for (int b0 = 0; b0 < deg; b0 += 32) {
        int ne = deg - b0; if (ne > 32) ne = 32;

        // sender id for this lane's edge (coalesced)
        int s_my = (lane < ne) ? __ldg(&binrow[b0 + lane]) : 0;

        // ---- Phase A1: cooperative x-row staging (4 lanes share one 64B row/line) ----
        #pragma unroll
        for (int k = 0; k < 4; k++) {
            int e8 = k * 8 + egrp;
            int se = __shfl_sync(0xffffffffu, s_my, e8);
            if (e8 < ne) {
                float4 v = __ldg(&x4[se * 4 + chunk]);
                *reinterpret_cast<float4*>(sXv + e8 * 20 + chunk * 4) = v;
            }
        }

        // ---- Phase A2: lane = edge. Compute SH once, stage Y. ----
        if (lane < ne) {
            float4 sp = g_pos4[s_my];
            float dx = rx - sp.x;
            float dy = ry - sp.y;
            float dz = rz - sp.z;
            float n2 = dx * dx + dy * dy + dz * dz;
            float inv = (n2 > 0.f) ? rsqrtf(n2) : 0.f;
            float X = dx * inv, Y = dy * inv, Z = dz * inv;
            float xx = X * X, yy = Y * Y, zz = Z * Z;
            float fz1 = 5.f * zz - 1.f;

            float4* yd = reinterpret_cast<float4*>(sY + lane * 20);
            yd[0] = make_float4(1.f, s3 * X, s3 * Y, s3 * Z);
            yd[1] = make_float4(s15 * X * Y, s15 * Y * Z,
                                0.5f * s5 * (3.f * zz - 1.f), s15 * X * Z);
            yd[2] = make_float4(0.5f * s15 * (xx - yy),
                                s35_8 * Y * (3.f * xx - yy),
                                s105 * X * Y * Z,
                                s21_8 * Y * fz1);
            yd[3] = make_float4(0.5f * s7 * Z * (5.f * zz - 3.f),
                                s21_8 * X * fz1,
                                0.5f * s105 * Z * (xx - yy),
                                s35_8 * X * (xx - 3.f * yy));
        }
        __syncwarp();

        // ---- Phase B: lane = (h,u). Packed f32x2 rank-1 accumulation. ----
        #pragma unroll 4
        for (int e = 0; e < ne; e++) {
            float sval = sXv[e * 20 + u];
            unsigned long long sv2;
            asm("mov.b64 %0, {%1, %1};" : "=l"(sv2) : "f"(sval));
            ulonglong2 y01 = *reinterpret_cast<const ulonglong2*>(sY + e * 20 + h * 8);
            ulonglong2 y23 = *reinterpret_cast<const ulonglong2*>(sY + e * 20 + h * 8 + 4);
            FMA2(acc01, sv2, y01.x, acc01);
            FMA2(acc23, sv2, y01.y, acc23);
            FMA2(acc45, sv2, y23.x, acc45);
            FMA2(acc67, sv2, y23.y, acc67);
        }
        __syncwarp();
    }

    // unpack accumulators
    float acc[8];
    asm("mov.b64 {%0, %1}, %2;" : "=f"(acc[0]), "=f"(acc[1]) : "l"(acc01));
    asm("mov.b64 {%0, %1}, %2;" : "=f"(acc[2]), "=f"(acc[3]) : "l"(acc23));
    asm("mov.b64 {%0, %1}, %2;" : "=f"(acc[4]), "=f"(acc[5]) : "l"(acc45));
    asm("mov.b64 {%0, %1}, %2;" : "=f"(acc[6]), "=f"(acc[7]) : "l"(acc67));

    // ---- repurpose scratch: A[256] | Xrow[16] | Out[512] ----
    float* sA   = scr;
    float* sX   = scr + 256;
    float* sOut = scr + 272;

    __syncwarp();
    {
        float4* sa = reinterpret_cast<float4*>(sA + u * 16 + h * 8);
        sa[0] = make_float4(acc[0], acc[1], acc[2], acc[3]);
        sa[1] = make_float4(acc[4], acc[5], acc[6], acc[7]);
        if (h == 0) sX[u] = x[(size_t)n * 16 + u];
    }
    __syncwarp();

    // ---- node update: lane = output channel w ----
    int w = lane;
    const float4* a4 = reinterpret_cast<const float4*>(sA);

    // pass 0: l=0 pre-sum + l=1 (uses A[i0..3])
    {
        float p0 = 0.f, a1_0 = 0.f, a1_1 = 0.f, a1_2 = 0.f;
        #pragma unroll
        for (int uu = 0; uu < 16; uu++) {
            float4 A0 = a4[uu * 4 + 0];
            float wpre = sWpre0[uu * 32 + w];
            float wc1  = sWc[uu * 32 + w];
            p0   += A0.x * wpre;
            a1_0 += A0.y * wc1;  a1_1 += A0.z * wc1;  a1_2 += A0.w * wc1;
        }
        sOut[32 + w * 3 + 0] = a1_0;
        sOut[32 + w * 3 + 1] = a1_1;
        sOut[32 + w * 3 + 2] = a1_2;
        // l=0: gelu -> post + shortcut
        float g = 1.5335290f * p0 * normcdff(p0);
        float q0 = 0.f;
        #pragma unroll
        for (int v = 0; v < 32; v++) {
            float gv = __shfl_sync(0xffffffffu, g, v);
            q0 += gv * sWpost0[v * 32 + w];
        }
        #pragma unroll
        for (int uu = 0; uu < 16; uu++) q0 += sX[uu] * sWsc[uu * 32 + w];
        sOut[w] = q0;
    }
    // pass 1: l=2 (A[i4..8])
    {
        float a0=0.f, a1=0.f, a2=0.f, a3=0.f, a4v=0.f;
        #pragma unroll
        for (int uu = 0; uu < 16; uu++) {
            float wc2 = sWc[512 + uu * 32 + w];
            float4 A1 = a4[uu * 4 + 1];
            float  A8 = sA[uu * 16 + 8];
            a0 += A1.x * wc2;  a1 += A1.y * wc2;  a2 += A1.z * wc2;
            a3 += A1.w * wc2;  a4v += A8 * wc2;
        }
        sOut[128 + w * 5 + 0] = a0;
        sOut[128 + w * 5 + 1] = a1;
        sOut[128 + w * 5 + 2] = a2;
        sOut[128 + w * 5 + 3] = a3;
        sOut[128 + w * 5 + 4] = a4v;
    }
    // pass 2: l=3 (A[i9..15])
    {
        float a0=0.f, a1=0.f, a2=0.f, a3=0.f, a4v=0.f, a5=0.f, a6=0.f;
        #pragma unroll
        for (int uu = 0; uu < 16; uu++) {
            float wc3 = sWc[1024 + uu * 32 + w];
            float4 A2 = a4[uu * 4 + 2];
            float4 A3 = a4[uu * 4 + 3];
            a0 += A2.y * wc3;  a1 += A2.z * wc3;  a2 += A2.w * wc3;
            a3 += A3.x * wc3;  a4v += A3.y * wc3; a5 += A3.z * wc3;
            a6 += A3.w * wc3;
        }
        sOut[288 + w * 7 + 0] = a0;
        sOut[288 + w * 7 + 1] = a1;
        sOut[288 + w * 7 + 2] = a2;
        sOut[288 + w * 7 + 3] = a3;
        sOut[288 + w * 7 + 4] = a4v;
        sOut[288 + w * 7 + 5] = a5;
        sOut[288 + w * 7 + 6] = a6;
    }
    __syncwarp();

    float4*       o4  = reinterpret_cast<float4*>(out + (size_t)n * 512);
    const float4* so4 = reinterpret_cast<const float4*>(sOut);
    #pragma unroll
    for (int k = 0; k < 4; k++) o4[w + 32 * k] = so4[w + 32 * k];
}

extern "C" void kernel_launch(void* const* d_in, const int* in_sizes, int n_in,
                              void* d_out, int out_size) {
    const float* x        = (const float*)d_in[0];
    const float* pos      = (const float*)d_in[1];
    const float* W_pre    = (const float*)d_in[2];
    const float* W_post   = (const float*)d_in[3];
    const float* W_sc     = (const float*)d_in[4];
    const int*   senders  = (const int*)d_in[5];
    const int*   receivers= (const int*)d_in[6];
    int E = in_sizes[5];
    float* out = (float*)d_out;

    zero_count_kernel<<<32, 1024>>>();
    pos4_kernel<<<32, 1024>>>(pos);
    scatter_bin_kernel<<<(E + 255) / 256, 256>>>(senders, receivers, E);
    wc_kernel<<<3, 512>>>(W_pre, W_post);
    fused_kernel<<<NNODES / 8, 256>>>(x, W_pre, W_post, W_sc, out);
}